// round 1
// baseline (speedup 1.0000x reference)
#include <cuda_runtime.h>
#include <math.h>

#define BB 32
#define MM 8192
#define II 256
#define BLOCKS_PER_B 8
#define WARPS_PER_BLOCK 8
#define PPB (BLOCKS_PER_B * WARPS_PER_BLOCK)   /* 64 partials per batch */
#define ROWS_PER_WARP (MM / PPB)               /* 128 */

/* Static device scratch (no allocations allowed in kernel_launch). */
__device__ float g_pk[BB * II];                /* projected key, 32 KB  */
__device__ float g_acc[BB * PPB * II];         /* partial accumulators, 2 MB */
__device__ float g_ms[BB * PPB];               /* partial running max   */
__device__ float g_ls[BB * PPB];               /* partial running sum   */
__device__ float g_bmax[BB];                   /* final per-batch max   */
__device__ float g_bsum[BB];                   /* final per-batch sum   */

/* ------------------------------------------------------------------ */
/* 1) projected_key = tanh(key @ W^T + b)                              */
/*    grid = B, block = 256 (thread i -> output feature i)             */
/* ------------------------------------------------------------------ */
__global__ void proj_kernel(const float* __restrict__ key,
                            const float* __restrict__ W,
                            const float* __restrict__ bias)
{
    __shared__ float sk[II];
    const int b = blockIdx.x;
    const int i = threadIdx.x;
    sk[i] = key[b * II + i];
    __syncthreads();

    const float* wr = W + (size_t)i * II;   /* torch Linear weight: [out, in] */
    float acc = bias[i];
#pragma unroll 8
    for (int k = 0; k < II; k++)
        acc = fmaf(sk[k], __ldg(&wr[k]), acc);

    g_pk[b * II + i] = tanhf(acc);
}

/* ------------------------------------------------------------------ */
/* 2) Single pass over memory: similarity + online-softmax partials.   */
/*    grid = B*BLOCKS_PER_B, block = 256 (8 warps). Warp-per-row.      */
/*    Lane l owns columns {4l..4l+3, 128+4l..128+4l+3} of the row and  */
/*    of the 256-wide accumulator.                                     */
/* ------------------------------------------------------------------ */
__global__ void __launch_bounds__(256, 4)
main_kernel(const float* __restrict__ memory,
            const float* __restrict__ beta,
            float* __restrict__ sim_out)
{
    const int b    = blockIdx.x / BLOCKS_PER_B;
    const int blk  = blockIdx.x % BLOCKS_PER_B;
    const int warp = threadIdx.x >> 5;
    const int lane = threadIdx.x & 31;
    const int p    = blk * WARPS_PER_BLOCK + warp;   /* 0..63 */

    const float4* pkv = (const float4*)(g_pk + b * II);
    const float4  pk0 = pkv[lane];
    const float4  pk1 = pkv[32 + lane];
    const float   bet = beta[b];

    const size_t  row0 = (size_t)p * ROWS_PER_WARP;
    const float4* base = (const float4*)(memory + ((size_t)b * MM + row0) * II);
    float*        srow = sim_out + (size_t)b * MM + row0;

    float  ms = -INFINITY, ls = 0.0f;
    float4 a0 = make_float4(0.f, 0.f, 0.f, 0.f);
    float4 a1 = make_float4(0.f, 0.f, 0.f, 0.f);

#pragma unroll 2
    for (int r = 0; r < ROWS_PER_WARP; r++) {
        const float4* mp = base + (size_t)r * (II / 4);
        const float4  x0 = mp[lane];
        const float4  x1 = mp[32 + lane];

        /* squared distance contribution of this lane's 8 columns */
        float t, d;
        t = pk0.x - x0.x; d  = t * t;
        t = pk0.y - x0.y; d += t * t;
        t = pk0.z - x0.z; d += t * t;
        t = pk0.w - x0.w; d += t * t;
        t = pk1.x - x1.x; d += t * t;
        t = pk1.y - x1.y; d += t * t;
        t = pk1.z - x1.z; d += t * t;
        t = pk1.w - x1.w; d += t * t;

        /* butterfly reduce -> every lane holds full d */
        d += __shfl_xor_sync(0xffffffffu, d, 16);
        d += __shfl_xor_sync(0xffffffffu, d, 8);
        d += __shfl_xor_sync(0xffffffffu, d, 4);
        d += __shfl_xor_sync(0xffffffffu, d, 2);
        d += __shfl_xor_sync(0xffffffffu, d, 1);

        if (lane == 0) srow[r] = -d;       /* similarity output */

        const float s = -bet * d;          /* softmax logit (TEMPERATURE=1) */

        if (s > ms) {                      /* new max: rescale state, w = 1 */
            const float c = __expf(ms - s);
            ls = ls * c + 1.0f;
            a0.x = fmaf(a0.x, c, x0.x); a0.y = fmaf(a0.y, c, x0.y);
            a0.z = fmaf(a0.z, c, x0.z); a0.w = fmaf(a0.w, c, x0.w);
            a1.x = fmaf(a1.x, c, x1.x); a1.y = fmaf(a1.y, c, x1.y);
            a1.z = fmaf(a1.z, c, x1.z); a1.w = fmaf(a1.w, c, x1.w);
            ms = s;
        } else {
            const float w = __expf(s - ms);
            ls += w;
            a0.x = fmaf(w, x0.x, a0.x); a0.y = fmaf(w, x0.y, a0.y);
            a0.z = fmaf(w, x0.z, a0.z); a0.w = fmaf(w, x0.w, a0.w);
            a1.x = fmaf(w, x1.x, a1.x); a1.y = fmaf(w, x1.y, a1.y);
            a1.z = fmaf(w, x1.z, a1.z); a1.w = fmaf(w, x1.w, a1.w);
        }
    }

    float4* accp = (float4*)(g_acc + ((size_t)(b * PPB + p)) * II);
    accp[lane]      = a0;
    accp[32 + lane] = a1;
    if (lane == 0) {
        g_ms[b * PPB + p] = ms;
        g_ls[b * PPB + p] = ls;
    }
}

/* ------------------------------------------------------------------ */
/* 3) Merge 64 partials per batch -> read_vector + (bmax, bsum).       */
/*    grid = B, block = 256 (thread i -> column i)                     */
/* ------------------------------------------------------------------ */
__global__ void combine_kernel(float* __restrict__ read_out)
{
    __shared__ float sm[PPB];
    __shared__ float sscale[PPB];
    __shared__ float sred[2];

    const int b = blockIdx.x;
    const int t = threadIdx.x;

    if (t < PPB) sm[t] = g_ms[b * PPB + t];
    __syncthreads();

    if (t == 0) {
        float m = -INFINITY;
        for (int q = 0; q < PPB; q++) m = fmaxf(m, sm[q]);
        sred[0] = m;
    }
    __syncthreads();
    const float Mb = sred[0];

    if (t < PPB) sscale[t] = __expf(sm[t] - Mb);
    __syncthreads();

    if (t == 0) {
        float su = 0.0f;
        for (int q = 0; q < PPB; q++) su += g_ls[b * PPB + q] * sscale[q];
        g_bmax[b] = Mb;
        g_bsum[b] = su;
        sred[1] = su;
    }
    __syncthreads();
    const float su = sred[1];

    float acc = 0.0f;
#pragma unroll 8
    for (int q = 0; q < PPB; q++)
        acc = fmaf(g_acc[((size_t)(b * PPB + q)) * II + t], sscale[q], acc);

    read_out[b * II + t] = acc / su;
}

/* ------------------------------------------------------------------ */
/* 4) weights[b,m] = exp(beta*sim - bmax) / bsum  (reads 1MB sim)      */
/* ------------------------------------------------------------------ */
__global__ void weights_kernel(const float* __restrict__ beta,
                               const float* __restrict__ sim,
                               float* __restrict__ wout)
{
    const int idx = blockIdx.x * blockDim.x + threadIdx.x;
    const int b   = idx / MM;
    const float inv = 1.0f / g_bsum[b];
    wout[idx] = __expf(beta[b] * sim[idx] - g_bmax[b]) * inv;
}

/* ------------------------------------------------------------------ */
extern "C" void kernel_launch(void* const* d_in, const int* in_sizes, int n_in,
                              void* d_out, int out_size)
{
    const float* memory = (const float*)d_in[0];   /* [B, M, I] */
    const float* key    = (const float*)d_in[1];   /* [B, I]    */
    const float* beta   = (const float*)d_in[2];   /* [B]       */
    const float* W      = (const float*)d_in[3];   /* [I, I]    */
    const float* bias   = (const float*)d_in[4];   /* [I]       */

    float* out      = (float*)d_out;
    float* w_out    = out;                         /* weights     [B, M] */
    float* read_out = out + (size_t)BB * MM;       /* read_vector [B, I] */
    float* sim_out  = read_out + (size_t)BB * II;  /* similarity  [B, M] */

    proj_kernel   <<<BB, II>>>(key, W, bias);
    main_kernel   <<<BB * BLOCKS_PER_B, 256>>>(memory, beta, sim_out);
    combine_kernel<<<BB, II>>>(read_out);
    weights_kernel<<<(BB * MM) / 256, 256>>>(beta, sim_out, w_out);
}

// round 3
// speedup vs baseline: 1.2453x; 1.2453x over previous
#include <cuda_runtime.h>
#include <math.h>

#define BB 32
#define MM 8192
#define II 256
#define BLOCKS_PER_B 32
#define WARPS_PER_BLOCK 8
#define PPB (BLOCKS_PER_B * WARPS_PER_BLOCK)   /* 256 partials per batch */
#define ROWS_PER_WARP (MM / PPB)               /* 32 */

/* Static device scratch (no allocations allowed). */
__device__ float g_pk[BB * II];                /* projected key, 32 KB   */
__device__ float g_acc[BB * PPB * II];         /* partial accums, 8 MB   */
__device__ float g_ms[BB * PPB];               /* partial running max    */
__device__ float g_ls[BB * PPB];               /* partial running sum    */
__device__ float g_bmax[BB];                   /* final per-batch max    */
__device__ float g_bsum[BB];                   /* final per-batch sum    */

/* ------------------------------------------------------------------ */
/* 1) projected_key = tanh(key @ W^T + b)   grid=B, block=256          */
/* ------------------------------------------------------------------ */
__global__ void proj_kernel(const float* __restrict__ key,
                            const float* __restrict__ W,
                            const float* __restrict__ bias)
{
    __shared__ float sk[II];
    const int b = blockIdx.x;
    const int i = threadIdx.x;
    sk[i] = key[b * II + i];
    __syncthreads();

    const float* wr = W + (size_t)i * II;   /* torch Linear weight: [out, in] */
    float acc = bias[i];
#pragma unroll 8
    for (int k = 0; k < II; k++)
        acc = fmaf(sk[k], __ldg(&wr[k]), acc);

    g_pk[b * II + i] = tanhf(acc);
}

/* ------------------------------------------------------------------ */
/* 2) Single pass over memory: similarity + online-softmax partials.   */
/*    grid = B*32, block = 256 (8 warps). Warp-per-row, 4 rows/iter.   */
/*    Lane l owns columns {4l..4l+3, 128+4l..128+4l+3}.                */
/* ------------------------------------------------------------------ */
__global__ void __launch_bounds__(256, 3)
main_kernel(const float* __restrict__ memory,
            const float* __restrict__ beta,
            float* __restrict__ sim_out)
{
    const int b    = blockIdx.x / BLOCKS_PER_B;
    const int blk  = blockIdx.x % BLOCKS_PER_B;
    const int warp = threadIdx.x >> 5;
    const int lane = threadIdx.x & 31;
    const int p    = blk * WARPS_PER_BLOCK + warp;   /* 0..255 */

    const float4* pkv = (const float4*)(g_pk + b * II);
    const float4  pk0 = pkv[lane];
    const float4  pk1 = pkv[32 + lane];
    const float   bet = beta[b];

    const size_t  row0 = (size_t)p * ROWS_PER_WARP;
    const float4* base = (const float4*)(memory + ((size_t)b * MM + row0) * II);
    float4*       srow = (float4*)(sim_out + (size_t)b * MM + row0);

    float  ms = -INFINITY, ls = 0.0f;
    float4 a0 = make_float4(0.f, 0.f, 0.f, 0.f);
    float4 a1 = make_float4(0.f, 0.f, 0.f, 0.f);

    for (int r = 0; r < ROWS_PER_WARP; r += 4) {
        /* ---- load 4 rows (8 independent float4 loads) ---- */
        const float4* mp0 = base + (size_t)(r + 0) * (II / 4);
        const float4* mp1 = base + (size_t)(r + 1) * (II / 4);
        const float4* mp2 = base + (size_t)(r + 2) * (II / 4);
        const float4* mp3 = base + (size_t)(r + 3) * (II / 4);
        const float4 x00 = mp0[lane], x01 = mp0[32 + lane];
        const float4 x10 = mp1[lane], x11 = mp1[32 + lane];
        const float4 x20 = mp2[lane], x21 = mp2[32 + lane];
        const float4 x30 = mp3[lane], x31 = mp3[32 + lane];

        /* ---- per-lane squared-diff partials for 4 rows ---- */
        float t;
        float d0, d1, d2, d3;
        t = pk0.x - x00.x; d0  = t * t;  t = pk0.x - x10.x; d1  = t * t;
        t = pk0.x - x20.x; d2  = t * t;  t = pk0.x - x30.x; d3  = t * t;
        t = pk0.y - x00.y; d0 += t * t;  t = pk0.y - x10.y; d1 += t * t;
        t = pk0.y - x20.y; d2 += t * t;  t = pk0.y - x30.y; d3 += t * t;
        t = pk0.z - x00.z; d0 += t * t;  t = pk0.z - x10.z; d1 += t * t;
        t = pk0.z - x20.z; d2 += t * t;  t = pk0.z - x30.z; d3 += t * t;
        t = pk0.w - x00.w; d0 += t * t;  t = pk0.w - x10.w; d1 += t * t;
        t = pk0.w - x20.w; d2 += t * t;  t = pk0.w - x30.w; d3 += t * t;
        t = pk1.x - x01.x; d0 += t * t;  t = pk1.x - x11.x; d1 += t * t;
        t = pk1.x - x21.x; d2 += t * t;  t = pk1.x - x31.x; d3 += t * t;
        t = pk1.y - x01.y; d0 += t * t;  t = pk1.y - x11.y; d1 += t * t;
        t = pk1.y - x21.y; d2 += t * t;  t = pk1.y - x31.y; d3 += t * t;
        t = pk1.z - x01.z; d0 += t * t;  t = pk1.z - x11.z; d1 += t * t;
        t = pk1.z - x21.z; d2 += t * t;  t = pk1.z - x31.z; d3 += t * t;
        t = pk1.w - x01.w; d0 += t * t;  t = pk1.w - x11.w; d1 += t * t;
        t = pk1.w - x21.w; d2 += t * t;  t = pk1.w - x31.w; d3 += t * t;

        /* ---- 4 interleaved butterfly reduces (shuffles pipeline) ---- */
#pragma unroll
        for (int sh = 16; sh >= 1; sh >>= 1) {
            d0 += __shfl_xor_sync(0xffffffffu, d0, sh);
            d1 += __shfl_xor_sync(0xffffffffu, d1, sh);
            d2 += __shfl_xor_sync(0xffffffffu, d2, sh);
            d3 += __shfl_xor_sync(0xffffffffu, d3, sh);
        }

        if (lane == 0)
            srow[r >> 2] = make_float4(-d0, -d1, -d2, -d3);  /* similarity */

        const float s0 = -bet * d0, s1 = -bet * d1;
        const float s2 = -bet * d2, s3 = -bet * d3;

        /* ---- one rescale per 4 rows ---- */
        const float m4 = fmaxf(fmaxf(s0, s1), fmaxf(s2, s3));
        if (m4 > ms) {
            const float c = __expf(ms - m4);   /* first iter: exp(-inf)=0 */
            ls *= c;
            a0.x *= c; a0.y *= c; a0.z *= c; a0.w *= c;
            a1.x *= c; a1.y *= c; a1.z *= c; a1.w *= c;
            ms = m4;
        }
        const float w0 = __expf(s0 - ms);
        const float w1 = __expf(s1 - ms);
        const float w2 = __expf(s2 - ms);
        const float w3 = __expf(s3 - ms);
        ls += (w0 + w1) + (w2 + w3);

        a0.x = fmaf(w0, x00.x, fmaf(w1, x10.x, fmaf(w2, x20.x, fmaf(w3, x30.x, a0.x))));
        a0.y = fmaf(w0, x00.y, fmaf(w1, x10.y, fmaf(w2, x20.y, fmaf(w3, x30.y, a0.y))));
        a0.z = fmaf(w0, x00.z, fmaf(w1, x10.z, fmaf(w2, x20.z, fmaf(w3, x30.z, a0.z))));
        a0.w = fmaf(w0, x00.w, fmaf(w1, x10.w, fmaf(w2, x20.w, fmaf(w3, x30.w, a0.w))));
        a1.x = fmaf(w0, x01.x, fmaf(w1, x11.x, fmaf(w2, x21.x, fmaf(w3, x31.x, a1.x))));
        a1.y = fmaf(w0, x01.y, fmaf(w1, x11.y, fmaf(w2, x21.y, fmaf(w3, x31.y, a1.y))));
        a1.z = fmaf(w0, x01.z, fmaf(w1, x11.z, fmaf(w2, x21.z, fmaf(w3, x31.z, a1.z))));
        a1.w = fmaf(w0, x01.w, fmaf(w1, x11.w, fmaf(w2, x21.w, fmaf(w3, x31.w, a1.w))));
    }

    float4* accp = (float4*)(g_acc + ((size_t)(b * PPB + p)) * II);
    accp[lane]      = a0;
    accp[32 + lane] = a1;
    if (lane == 0) {
        g_ms[b * PPB + p] = ms;
        g_ls[b * PPB + p] = ls;
    }
}

/* ------------------------------------------------------------------ */
/* 3) Merge 256 partials per batch -> read_vector + (bmax, bsum).      */
/*    grid = B, block = 256 (thread t -> column t)                     */
/* ------------------------------------------------------------------ */
__global__ void combine_kernel(float* __restrict__ read_out)
{
    __shared__ float sscale[PPB];
    __shared__ float sred[32];
    __shared__ float sbroad[2];

    const int b    = blockIdx.x;
    const int t    = threadIdx.x;
    const int lane = t & 31;
    const int wrp  = t >> 5;

    /* block max over 256 partial maxima */
    float m = g_ms[b * PPB + t];
    float mv = m;
#pragma unroll
    for (int sh = 16; sh >= 1; sh >>= 1)
        mv = fmaxf(mv, __shfl_xor_sync(0xffffffffu, mv, sh));
    if (lane == 0) sred[wrp] = mv;
    __syncthreads();
    if (t == 0) {
        float mm = sred[0];
        for (int q = 1; q < 8; q++) mm = fmaxf(mm, sred[q]);
        sbroad[0] = mm;
    }
    __syncthreads();
    const float Mb = sbroad[0];

    const float sc = __expf(m - Mb);
    sscale[t] = sc;

    /* block sum of ls * scale */
    float sv = g_ls[b * PPB + t] * sc;
#pragma unroll
    for (int sh = 16; sh >= 1; sh >>= 1)
        sv += __shfl_xor_sync(0xffffffffu, sv, sh);
    if (lane == 0) sred[wrp] = sv;
    __syncthreads();
    if (t == 0) {
        float su = 0.0f;
        for (int q = 0; q < 8; q++) su += sred[q];
        g_bmax[b] = Mb;
        g_bsum[b] = su;
        sbroad[1] = su;
    }
    __syncthreads();
    const float su = sbroad[1];

    /* column t of read_vector: merge 256 partial accumulators */
    float acc = 0.0f;
    const float* ap = g_acc + (size_t)b * PPB * II + t;
#pragma unroll 8
    for (int q = 0; q < PPB; q++)
        acc = fmaf(ap[(size_t)q * II], sscale[q], acc);

    read_out[b * II + t] = acc / su;
}

/* ------------------------------------------------------------------ */
/* 4) weights[b,m] = exp(beta*sim - bmax) / bsum                       */
/* ------------------------------------------------------------------ */
__global__ void weights_kernel(const float* __restrict__ beta,
                               const float* __restrict__ sim,
                               float* __restrict__ wout)
{
    const int idx = blockIdx.x * blockDim.x + threadIdx.x;
    const int b   = idx / MM;
    const float inv = 1.0f / g_bsum[b];
    wout[idx] = __expf(beta[b] * sim[idx] - g_bmax[b]) * inv;
}

/* ------------------------------------------------------------------ */
extern "C" void kernel_launch(void* const* d_in, const int* in_sizes, int n_in,
                              void* d_out, int out_size)
{
    const float* memory = (const float*)d_in[0];   /* [B, M, I] */
    const float* key    = (const float*)d_in[1];   /* [B, I]    */
    const float* beta   = (const float*)d_in[2];   /* [B]       */
    const float* W      = (const float*)d_in[3];   /* [I, I]    */
    const float* bias   = (const float*)d_in[4];   /* [I]       */

    float* out      = (float*)d_out;
    float* w_out    = out;                         /* weights     [B, M] */
    float* read_out = out + (size_t)BB * MM;       /* read_vector [B, I] */
    float* sim_out  = read_out + (size_t)BB * II;  /* similarity  [B, M] */

    proj_kernel   <<<BB, II>>>(key, W, bias);
    main_kernel   <<<BB * BLOCKS_PER_B, 256>>>(memory, beta, sim_out);
    combine_kernel<<<BB, II>>>(read_out);
    weights_kernel<<<(BB * MM) / 256, 256>>>(beta, sim_out, w_out);
}